// round 1
// baseline (speedup 1.0000x reference)
#include <cuda_runtime.h>
#include <float.h>
#include <math.h>

#define HH 8
#define CC 128
#define MAXN 65536

// Scratch (allocation-free): p = x@W[:C], q = x@W[C:], per-(node,head) max and sum.
__device__ float g_p[MAXN * HH];
__device__ float g_q[MAXN * HH];
__device__ float g_m[MAXN * HH];
__device__ float g_s[MAXN * HH];

// ---------------------------------------------------------------------------
// atomic float max via signed/unsigned int monotonicity trick
// ---------------------------------------------------------------------------
__device__ __forceinline__ void atomicMaxF(float* addr, float v) {
    if (v >= 0.0f)
        atomicMax((int*)addr, __float_as_int(v));
    else
        atomicMin((unsigned int*)addr, __float_as_uint(v));
}

// ---------------------------------------------------------------------------
// K0: init m = -FLT_MAX, s = 0  (must run every graph replay)
// ---------------------------------------------------------------------------
__global__ void k_init(float* __restrict__ m, float* __restrict__ s, int n8) {
    int i = blockIdx.x * blockDim.x + threadIdx.x;
    if (i < n8) { m[i] = -FLT_MAX; s[i] = 0.0f; }
}

// ---------------------------------------------------------------------------
// K1: p[n] = x[n] @ W[0:128], q[n] = x[n] @ W[128:256]   (one warp per node)
// W is [256, 8] row-major. Stored transposed in shared: ws[k][c], k<8 -> Wp
// head k, k>=8 -> Wq head k-8. Conflict-free LDS (consecutive c per lane).
// ---------------------------------------------------------------------------
__global__ void k_gemm(const float* __restrict__ x, const float* __restrict__ W,
                       float* __restrict__ p, float* __restrict__ q, int N) {
    __shared__ float ws[16][CC];
    for (int i = threadIdx.x; i < 256 * HH; i += blockDim.x) {
        int c = i / HH, h = i % HH;
        if (c < CC) ws[h][c] = W[i];
        else        ws[HH + h][c - CC] = W[i];
    }
    __syncthreads();

    int gwarp  = (blockIdx.x * blockDim.x + threadIdx.x) >> 5;
    int lane   = threadIdx.x & 31;
    int nwarps = (gridDim.x * blockDim.x) >> 5;

    for (int n = gwarp; n < N; n += nwarps) {
        float xv[4];
#pragma unroll
        for (int j = 0; j < 4; j++) xv[j] = x[n * CC + lane + 32 * j];

        float acc[16];
#pragma unroll
        for (int k = 0; k < 16; k++) acc[k] = 0.0f;
#pragma unroll
        for (int j = 0; j < 4; j++) {
            int c = lane + 32 * j;
#pragma unroll
            for (int k = 0; k < 16; k++) acc[k] += xv[j] * ws[k][c];
        }
        // full butterfly: every lane ends with the complete 16 sums
#pragma unroll
        for (int off = 16; off; off >>= 1)
#pragma unroll
            for (int k = 0; k < 16; k++)
                acc[k] += __shfl_xor_sync(0xffffffffu, acc[k], off);

        if (lane < HH)                 p[n * HH + lane]        = acc[lane];
        else if (lane < 2 * HH)        q[n * HH + (lane - HH)] = acc[lane];
    }
}

// ---------------------------------------------------------------------------
// K2 (pass A): alpha = leaky(relu slope .2)((p[r]+q[c]+b)*|ea|)*100
//   -> write alpha to out, atomicMax per-(r,h), write row/col outputs.
// ---------------------------------------------------------------------------
__global__ void k_passA(const int* __restrict__ row, const int* __restrict__ col,
                        const float* __restrict__ ea,
                        const float* __restrict__ p, const float* __restrict__ q,
                        const float* __restrict__ b,
                        float* __restrict__ m, float* __restrict__ out,
                        int E, int M, int writeIdx) {
    int e = blockIdx.x * blockDim.x + threadIdx.x;
    if (e >= M) return;
    int r, c; float w;
    if (e < E) { r = row[e]; c = col[e]; w = fabsf(ea[e]); }
    else       { r = e - E;  c = r;      w = 1.0f; }

    float4 p0 = *(const float4*)(p + r * HH);
    float4 p1 = *(const float4*)(p + r * HH + 4);
    float4 q0 = *(const float4*)(q + c * HH);
    float4 q1 = *(const float4*)(q + c * HH + 4);

    float av[HH] = { p0.x + q0.x, p0.y + q0.y, p0.z + q0.z, p0.w + q0.w,
                     p1.x + q1.x, p1.y + q1.y, p1.z + q1.z, p1.w + q1.w };
#pragma unroll
    for (int h = 0; h < HH; h++) {
        float t = (av[h] + b[h]) * w;
        t = (t > 0.0f) ? t : 0.2f * t;
        t *= 100.0f;
        av[h] = t;
        atomicMaxF(&m[r * HH + h], t);
    }
    *(float4*)(out + (size_t)e * HH)     = make_float4(av[0], av[1], av[2], av[3]);
    *(float4*)(out + (size_t)e * HH + 4) = make_float4(av[4], av[5], av[6], av[7]);

    if (writeIdx) {
        out[(size_t)M * HH + e]     = (float)r;
        out[(size_t)M * HH + M + e] = (float)c;
    }
}

// ---------------------------------------------------------------------------
// K3 (pass B): s[r,h] += exp(alpha - m[r,h])   (no writeback of exp)
// ---------------------------------------------------------------------------
__global__ void k_passB(const int* __restrict__ row,
                        const float* __restrict__ m, float* __restrict__ s,
                        const float* __restrict__ out, int E, int M) {
    int e = blockIdx.x * blockDim.x + threadIdx.x;
    if (e >= M) return;
    int r = (e < E) ? row[e] : (e - E);
    float4 a0 = *(const float4*)(out + (size_t)e * HH);
    float4 a1 = *(const float4*)(out + (size_t)e * HH + 4);
    float av[HH] = { a0.x, a0.y, a0.z, a0.w, a1.x, a1.y, a1.z, a1.w };
#pragma unroll
    for (int h = 0; h < HH; h++) {
        float ev = __expf(av[h] - m[r * HH + h]);
        atomicAdd(&s[r * HH + h], ev);
    }
}

// ---------------------------------------------------------------------------
// K4 (pass C): out = exp(alpha - m[r]) / (s[r] + 1e-16)
// ---------------------------------------------------------------------------
__global__ void k_passC(const int* __restrict__ row,
                        const float* __restrict__ m, const float* __restrict__ s,
                        float* __restrict__ out, int E, int M) {
    int e = blockIdx.x * blockDim.x + threadIdx.x;
    if (e >= M) return;
    int r = (e < E) ? row[e] : (e - E);
    float4 a0 = *(const float4*)(out + (size_t)e * HH);
    float4 a1 = *(const float4*)(out + (size_t)e * HH + 4);
    float av[HH] = { a0.x, a0.y, a0.z, a0.w, a1.x, a1.y, a1.z, a1.w };
#pragma unroll
    for (int h = 0; h < HH; h++) {
        float ev = __expf(av[h] - m[r * HH + h]);
        av[h] = ev / (s[r * HH + h] + 1e-16f);
    }
    *(float4*)(out + (size_t)e * HH)     = make_float4(av[0], av[1], av[2], av[3]);
    *(float4*)(out + (size_t)e * HH + 4) = make_float4(av[4], av[5], av[6], av[7]);
}

// ---------------------------------------------------------------------------
extern "C" void kernel_launch(void* const* d_in, const int* in_sizes, int n_in,
                              void* d_out, int out_size) {
    const float* x  = (const float*)d_in[0];   // [N, 128]
    const int*   ei = (const int*)d_in[1];     // [2, E]
    const float* ea = (const float*)d_in[2];   // [E]
    const float* W  = (const float*)d_in[3];   // [256, 8]
    const float* b  = (const float*)d_in[4];   // [8]
    float* out = (float*)d_out;

    int N = in_sizes[0] / CC;
    int E = in_sizes[2];
    int M = E + N;
    const int* row = ei;
    const int* col = ei + E;

    float *p, *q, *m, *s;
    cudaGetSymbolAddress((void**)&p, g_p);
    cudaGetSymbolAddress((void**)&q, g_q);
    cudaGetSymbolAddress((void**)&m, g_m);
    cudaGetSymbolAddress((void**)&s, g_s);

    int writeIdx = (out_size >= M * (HH + 2)) ? 1 : 0;

    int n8 = N * HH;
    k_init<<<(n8 + 255) / 256, 256>>>(m, s, n8);

    // one warp per node, 8 warps per block
    int gblocks = (N + 7) / 8;
    k_gemm<<<gblocks, 256>>>(x, W, p, q, N);

    int eblocks = (M + 255) / 256;
    k_passA<<<eblocks, 256>>>(row, col, ea, p, q, b, m, out, E, M, writeIdx);
    k_passB<<<eblocks, 256>>>(row, m, s, out, E, M);
    k_passC<<<eblocks, 256>>>(row, m, s, out, E, M);
}

// round 3
// speedup vs baseline: 1.4326x; 1.4326x over previous
#include <cuda_runtime.h>
#include <cuda_bf16.h>
#include <float.h>
#include <math.h>

#define HH 8
#define CC 128
#define MAXN 65536

// Scratch (allocation-free):
// p = x@W[:C], q = x@W[C:]  (L2-resident, N*8 floats each)
// m = per-node packed bf16x2[4] running max, s = per-(node,head) f32 sum
__device__ float        g_p[MAXN * HH];
__device__ float        g_q[MAXN * HH];
__device__ unsigned int g_m[MAXN * 4];
__device__ float        g_s[MAXN * HH];

// ---------------------------------------------------------------------------
// vectorized reductions (sm_90+)
// ---------------------------------------------------------------------------
__device__ __forceinline__ void redMaxBf16v2(unsigned int* addr,
                                             unsigned short lo, unsigned short hi) {
    asm volatile("red.global.max.noftz.v2.bf16 [%0], {%1, %2};"
                 :: "l"(addr), "h"(lo), "h"(hi) : "memory");
}
__device__ __forceinline__ void redAddV4(float* addr, float a, float b, float c, float d) {
    asm volatile("red.global.add.v4.f32 [%0], {%1, %2, %3, %4};"
                 :: "l"(addr), "f"(a), "f"(b), "f"(c), "f"(d) : "memory");
}

// bf16 (packed in u32) -> float: widen exactly by moving to high 16 bits
__device__ __forceinline__ float bfLo(unsigned int u) { return __uint_as_float(u << 16); }
__device__ __forceinline__ float bfHi(unsigned int u) { return __uint_as_float(u & 0xFFFF0000u); }

// ---------------------------------------------------------------------------
// alpha for one edge: av[8] = leaky_relu((p[r]+q[c]+b)*w, 0.2)*100
// ---------------------------------------------------------------------------
__device__ __forceinline__ void computeAlpha(const float* __restrict__ p,
                                             const float* __restrict__ q,
                                             const float* __restrict__ b,
                                             int r, int c, float w, float* av) {
    float4 p0 = *(const float4*)(p + r * HH);
    float4 p1 = *(const float4*)(p + r * HH + 4);
    float4 q0 = *(const float4*)(q + c * HH);
    float4 q1 = *(const float4*)(q + c * HH + 4);
    av[0] = p0.x + q0.x; av[1] = p0.y + q0.y; av[2] = p0.z + q0.z; av[3] = p0.w + q0.w;
    av[4] = p1.x + q1.x; av[5] = p1.y + q1.y; av[6] = p1.z + q1.z; av[7] = p1.w + q1.w;
#pragma unroll
    for (int h = 0; h < HH; h++) {
        float t = (av[h] + b[h]) * w;
        t = (t > 0.0f) ? t : 0.2f * t;
        av[h] = t * 100.0f;
    }
}

// ---------------------------------------------------------------------------
// K0: init m = packed bf16 -inf, s = 0
// ---------------------------------------------------------------------------
__global__ void k_init(unsigned int* __restrict__ m, float* __restrict__ s, int N) {
    int i = blockIdx.x * blockDim.x + threadIdx.x;
    if (i < N * HH) s[i] = 0.0f;
    if (i < N * 4)  m[i] = 0xFF80FF80u;   // bf16 -inf in both halves
}

// ---------------------------------------------------------------------------
// K1: p[n] = x[n] @ W[0:128], q[n] = x[n] @ W[128:256]   (one warp per node)
// ---------------------------------------------------------------------------
__global__ void k_gemm(const float* __restrict__ x, const float* __restrict__ W,
                       float* __restrict__ p, float* __restrict__ q, int N) {
    __shared__ float ws[16][CC];
    for (int i = threadIdx.x; i < 256 * HH; i += blockDim.x) {
        int c = i / HH, h = i % HH;
        if (c < CC) ws[h][c] = W[i];
        else        ws[HH + h][c - CC] = W[i];
    }
    __syncthreads();

    int gwarp  = (blockIdx.x * blockDim.x + threadIdx.x) >> 5;
    int lane   = threadIdx.x & 31;
    int nwarps = (gridDim.x * blockDim.x) >> 5;

    for (int n = gwarp; n < N; n += nwarps) {
        float xv[4];
#pragma unroll
        for (int j = 0; j < 4; j++) xv[j] = x[n * CC + lane + 32 * j];

        float acc[16];
#pragma unroll
        for (int k = 0; k < 16; k++) acc[k] = 0.0f;
#pragma unroll
        for (int j = 0; j < 4; j++) {
            int c = lane + 32 * j;
#pragma unroll
            for (int k = 0; k < 16; k++) acc[k] += xv[j] * ws[k][c];
        }
#pragma unroll
        for (int off = 16; off; off >>= 1)
#pragma unroll
            for (int k = 0; k < 16; k++)
                acc[k] += __shfl_xor_sync(0xffffffffu, acc[k], off);

        if (lane < HH)          p[n * HH + lane]        = acc[lane];
        else if (lane < 2 * HH) q[n * HH + (lane - HH)] = acc[lane];
    }
}

// ---------------------------------------------------------------------------
// K2 (pass A): compute alpha, packed v2.bf16 red.max into m (4 reds/edge)
// ---------------------------------------------------------------------------
__global__ void k_passA(const int* __restrict__ row, const int* __restrict__ col,
                        const float* __restrict__ ea,
                        const float* __restrict__ p, const float* __restrict__ q,
                        const float* __restrict__ b,
                        unsigned int* __restrict__ m, int E, int M) {
    int e = blockIdx.x * blockDim.x + threadIdx.x;
    if (e >= M) return;
    int r, c; float w;
    if (e < E) { r = row[e]; c = col[e]; w = fabsf(ea[e]); }
    else       { r = e - E;  c = r;      w = 1.0f; }

    float av[HH];
    computeAlpha(p, q, b, r, c, w, av);

#pragma unroll
    for (int k = 0; k < 4; k++) {
        __nv_bfloat16 lo = __float2bfloat16_rn(av[2 * k]);
        __nv_bfloat16 hi = __float2bfloat16_rn(av[2 * k + 1]);
        redMaxBf16v2(&m[r * 4 + k],
                     *(unsigned short*)&lo, *(unsigned short*)&hi);
    }
}

// ---------------------------------------------------------------------------
// K3 (pass B): recompute alpha, s[r] += exp(alpha - m[r])  (2 v4 reds/edge)
// ---------------------------------------------------------------------------
__global__ void k_passB(const int* __restrict__ row, const int* __restrict__ col,
                        const float* __restrict__ ea,
                        const float* __restrict__ p, const float* __restrict__ q,
                        const float* __restrict__ b,
                        const unsigned int* __restrict__ m, float* __restrict__ s,
                        int E, int M) {
    int e = blockIdx.x * blockDim.x + threadIdx.x;
    if (e >= M) return;
    int r, c; float w;
    if (e < E) { r = row[e]; c = col[e]; w = fabsf(ea[e]); }
    else       { r = e - E;  c = r;      w = 1.0f; }

    float av[HH];
    computeAlpha(p, q, b, r, c, w, av);

    uint4 mu = *(const uint4*)(m + r * 4);
    float mv[HH] = { bfLo(mu.x), bfHi(mu.x), bfLo(mu.y), bfHi(mu.y),
                     bfLo(mu.z), bfHi(mu.z), bfLo(mu.w), bfHi(mu.w) };
    float ev[HH];
#pragma unroll
    for (int h = 0; h < HH; h++) ev[h] = __expf(av[h] - mv[h]);

    redAddV4(&s[r * HH],     ev[0], ev[1], ev[2], ev[3]);
    redAddV4(&s[r * HH + 4], ev[4], ev[5], ev[6], ev[7]);
}

// ---------------------------------------------------------------------------
// K4 (pass C): recompute alpha, out = exp(alpha-m)/(s+1e-16); write row/col
// ---------------------------------------------------------------------------
__global__ void k_passC(const int* __restrict__ row, const int* __restrict__ col,
                        const float* __restrict__ ea,
                        const float* __restrict__ p, const float* __restrict__ q,
                        const float* __restrict__ b,
                        const unsigned int* __restrict__ m, const float* __restrict__ s,
                        float* __restrict__ out, int E, int M, int writeIdx) {
    int e = blockIdx.x * blockDim.x + threadIdx.x;
    if (e >= M) return;
    int r, c; float w;
    if (e < E) { r = row[e]; c = col[e]; w = fabsf(ea[e]); }
    else       { r = e - E;  c = r;      w = 1.0f; }

    float av[HH];
    computeAlpha(p, q, b, r, c, w, av);

    uint4 mu = *(const uint4*)(m + r * 4);
    float mv[HH] = { bfLo(mu.x), bfHi(mu.x), bfLo(mu.y), bfHi(mu.y),
                     bfLo(mu.z), bfHi(mu.z), bfLo(mu.w), bfHi(mu.w) };
    float4 s0 = *(const float4*)(s + r * HH);
    float4 s1 = *(const float4*)(s + r * HH + 4);
    float sv[HH] = { s0.x, s0.y, s0.z, s0.w, s1.x, s1.y, s1.z, s1.w };

#pragma unroll
    for (int h = 0; h < HH; h++)
        av[h] = __expf(av[h] - mv[h]) / (sv[h] + 1e-16f);

    *(float4*)(out + (size_t)e * HH)     = make_float4(av[0], av[1], av[2], av[3]);
    *(float4*)(out + (size_t)e * HH + 4) = make_float4(av[4], av[5], av[6], av[7]);

    if (writeIdx) {
        out[(size_t)M * HH + e]     = (float)r;
        out[(size_t)M * HH + M + e] = (float)c;
    }
}

// ---------------------------------------------------------------------------
extern "C" void kernel_launch(void* const* d_in, const int* in_sizes, int n_in,
                              void* d_out, int out_size) {
    const float* x  = (const float*)d_in[0];   // [N, 128]
    const int*   ei = (const int*)d_in[1];     // [2, E]
    const float* ea = (const float*)d_in[2];   // [E]
    const float* W  = (const float*)d_in[3];   // [256, 8]
    const float* b  = (const float*)d_in[4];   // [8]
    float* out = (float*)d_out;

    int N = in_sizes[0] / CC;
    int E = in_sizes[2];
    int M = E + N;
    const int* row = ei;
    const int* col = ei + E;

    float *p, *q, *s; unsigned int* m;
    cudaGetSymbolAddress((void**)&p, g_p);
    cudaGetSymbolAddress((void**)&q, g_q);
    cudaGetSymbolAddress((void**)&m, g_m);
    cudaGetSymbolAddress((void**)&s, g_s);

    int writeIdx = (out_size >= M * (HH + 2)) ? 1 : 0;

    k_init<<<(N * HH + 255) / 256, 256>>>(m, s, N);

    int gblocks = (N + 7) / 8;   // one warp per node, 8 warps/block
    k_gemm<<<gblocks, 256>>>(x, W, p, q, N);

    int eblocks = (M + 255) / 256;
    k_passA<<<eblocks, 256>>>(row, col, ea, p, q, b, m, E, M);
    k_passB<<<eblocks, 256>>>(row, col, ea, p, q, b, m, s, E, M);
    k_passC<<<eblocks, 256>>>(row, col, ea, p, q, b, m, s, out, E, M, writeIdx);
}

// round 4
// speedup vs baseline: 1.6025x; 1.1186x over previous
#include <cuda_runtime.h>
#include <cuda_bf16.h>
#include <float.h>
#include <math.h>

#define HH 8
#define CC 128
#define MAXN 65536

// Scratch (allocation-free):
// p = x@W[:C], q = x@W[C:]  (L2-resident, N*8 floats each)
// m = per-node 8 x bf16 running max (16B), s = per-(node,head) f32 sum
__device__ float        g_p[MAXN * HH];
__device__ float        g_q[MAXN * HH];
__device__ unsigned int g_m[MAXN * 4];
__device__ float        g_s[MAXN * HH];

// ---------------------------------------------------------------------------
// vectorized reductions (sm_90+)
// ---------------------------------------------------------------------------
__device__ __forceinline__ void redMaxBf16v8(unsigned int* addr, const unsigned short* h) {
    asm volatile("red.global.max.noftz.v8.bf16 [%0], {%1,%2,%3,%4,%5,%6,%7,%8};"
                 :: "l"(addr), "h"(h[0]), "h"(h[1]), "h"(h[2]), "h"(h[3]),
                    "h"(h[4]), "h"(h[5]), "h"(h[6]), "h"(h[7]) : "memory");
}
__device__ __forceinline__ void redAddV4(float* addr, float a, float b, float c, float d) {
    asm volatile("red.global.add.v4.f32 [%0], {%1, %2, %3, %4};"
                 :: "l"(addr), "f"(a), "f"(b), "f"(c), "f"(d) : "memory");
}

// bf16 (packed in u32) -> float: widen exactly by moving to high 16 bits
__device__ __forceinline__ float bfLo(unsigned int u) { return __uint_as_float(u << 16); }
__device__ __forceinline__ float bfHi(unsigned int u) { return __uint_as_float(u & 0xFFFF0000u); }

// ---------------------------------------------------------------------------
// K1: p[n] = x[n] @ W[0:128], q[n] = x[n] @ W[128:256]   (one warp per node)
//     also initializes m[n] = bf16 -inf x8, s[n] = 0 x8
// ---------------------------------------------------------------------------
__global__ void k_gemm(const float* __restrict__ x, const float* __restrict__ W,
                       float* __restrict__ p, float* __restrict__ q,
                       unsigned int* __restrict__ m, float* __restrict__ s, int N) {
    __shared__ float ws[16][CC];
    for (int i = threadIdx.x; i < 256 * HH; i += blockDim.x) {
        int c = i / HH, h = i % HH;
        if (c < CC) ws[h][c] = W[i];
        else        ws[HH + h][c - CC] = W[i];
    }
    __syncthreads();

    int gwarp  = (blockIdx.x * blockDim.x + threadIdx.x) >> 5;
    int lane   = threadIdx.x & 31;
    int nwarps = (gridDim.x * blockDim.x) >> 5;

    for (int n = gwarp; n < N; n += nwarps) {
        float xv[4];
#pragma unroll
        for (int j = 0; j < 4; j++) xv[j] = x[n * CC + lane + 32 * j];

        float acc[16];
#pragma unroll
        for (int k = 0; k < 16; k++) acc[k] = 0.0f;
#pragma unroll
        for (int j = 0; j < 4; j++) {
            int c = lane + 32 * j;
#pragma unroll
            for (int k = 0; k < 16; k++) acc[k] += xv[j] * ws[k][c];
        }
#pragma unroll
        for (int off = 16; off; off >>= 1)
#pragma unroll
            for (int k = 0; k < 16; k++)
                acc[k] += __shfl_xor_sync(0xffffffffu, acc[k], off);

        if (lane < HH)          p[n * HH + lane]        = acc[lane];
        else if (lane < 2 * HH) q[n * HH + (lane - HH)] = acc[lane];
        else if (lane < 24)     s[n * HH + (lane - 16)] = 0.0f;
        else if (lane == 24)    *(uint4*)(m + n * 4) =
                                    make_uint4(0xFF80FF80u, 0xFF80FF80u,
                                               0xFF80FF80u, 0xFF80FF80u);
    }
}

// ---------------------------------------------------------------------------
// K2 (pass A): alpha = leaky((p[r]+q[c]+b)*|ea|)*100 -> out (staged, L2-hot)
//              one v8.bf16 red.max per edge; also write row/col outputs
// ---------------------------------------------------------------------------
__global__ void k_passA(const int* __restrict__ row, const int* __restrict__ col,
                        const float* __restrict__ ea,
                        const float* __restrict__ p, const float* __restrict__ q,
                        const float* __restrict__ b,
                        unsigned int* __restrict__ m, float* __restrict__ out,
                        int E, int M, int writeIdx) {
    int e = blockIdx.x * blockDim.x + threadIdx.x;
    if (e >= M) return;
    int r, c; float w;
    if (e < E) { r = row[e]; c = col[e]; w = fabsf(ea[e]); }
    else       { r = e - E;  c = r;      w = 1.0f; }

    float4 p0 = *(const float4*)(p + r * HH);
    float4 p1 = *(const float4*)(p + r * HH + 4);
    float4 q0 = *(const float4*)(q + c * HH);
    float4 q1 = *(const float4*)(q + c * HH + 4);

    float av[HH] = { p0.x + q0.x, p0.y + q0.y, p0.z + q0.z, p0.w + q0.w,
                     p1.x + q1.x, p1.y + q1.y, p1.z + q1.z, p1.w + q1.w };
    unsigned short hb[HH];
#pragma unroll
    for (int h = 0; h < HH; h++) {
        float t = (av[h] + b[h]) * w;
        t = (t > 0.0f) ? t : 0.2f * t;
        t *= 100.0f;
        av[h] = t;
        __nv_bfloat16 bh = __float2bfloat16_rn(t);
        hb[h] = *(unsigned short*)&bh;
    }
    redMaxBf16v8(&m[r * 4], hb);

    *(float4*)(out + (size_t)e * HH)     = make_float4(av[0], av[1], av[2], av[3]);
    *(float4*)(out + (size_t)e * HH + 4) = make_float4(av[4], av[5], av[6], av[7]);

    if (writeIdx) {
        out[(size_t)M * HH + e]     = (float)r;
        out[(size_t)M * HH + M + e] = (float)c;
    }
}

// ---------------------------------------------------------------------------
// K3 (pass B): read staged alpha (coalesced, L2), gather m (1 scattered load),
//              ev = exp(alpha - m); s[r] += ev; write ev back in place
// ---------------------------------------------------------------------------
__global__ void k_passB(const int* __restrict__ row,
                        const unsigned int* __restrict__ m, float* __restrict__ s,
                        float* __restrict__ out, int E, int M) {
    int e = blockIdx.x * blockDim.x + threadIdx.x;
    if (e >= M) return;
    int r = (e < E) ? row[e] : (e - E);

    float4 a0 = *(const float4*)(out + (size_t)e * HH);
    float4 a1 = *(const float4*)(out + (size_t)e * HH + 4);
    float av[HH] = { a0.x, a0.y, a0.z, a0.w, a1.x, a1.y, a1.z, a1.w };

    uint4 mu = *(const uint4*)(m + r * 4);
    float mv[HH] = { bfLo(mu.x), bfHi(mu.x), bfLo(mu.y), bfHi(mu.y),
                     bfLo(mu.z), bfHi(mu.z), bfLo(mu.w), bfHi(mu.w) };
    float ev[HH];
#pragma unroll
    for (int h = 0; h < HH; h++) ev[h] = __expf(av[h] - mv[h]);

    redAddV4(&s[r * HH],     ev[0], ev[1], ev[2], ev[3]);
    redAddV4(&s[r * HH + 4], ev[4], ev[5], ev[6], ev[7]);

    *(float4*)(out + (size_t)e * HH)     = make_float4(ev[0], ev[1], ev[2], ev[3]);
    *(float4*)(out + (size_t)e * HH + 4) = make_float4(ev[4], ev[5], ev[6], ev[7]);
}

// ---------------------------------------------------------------------------
// K4 (pass C): read staged ev (coalesced), gather s (2 scattered), normalize
// ---------------------------------------------------------------------------
__global__ void k_passC(const int* __restrict__ row,
                        const float* __restrict__ s,
                        float* __restrict__ out, int E, int M) {
    int e = blockIdx.x * blockDim.x + threadIdx.x;
    if (e >= M) return;
    int r = (e < E) ? row[e] : (e - E);

    float4 e0 = *(const float4*)(out + (size_t)e * HH);
    float4 e1 = *(const float4*)(out + (size_t)e * HH + 4);
    float ev[HH] = { e0.x, e0.y, e0.z, e0.w, e1.x, e1.y, e1.z, e1.w };

    float4 s0 = *(const float4*)(s + r * HH);
    float4 s1 = *(const float4*)(s + r * HH + 4);
    float sv[HH] = { s0.x, s0.y, s0.z, s0.w, s1.x, s1.y, s1.z, s1.w };

#pragma unroll
    for (int h = 0; h < HH; h++)
        ev[h] = ev[h] / (sv[h] + 1e-16f);

    *(float4*)(out + (size_t)e * HH)     = make_float4(ev[0], ev[1], ev[2], ev[3]);
    *(float4*)(out + (size_t)e * HH + 4) = make_float4(ev[4], ev[5], ev[6], ev[7]);
}

// ---------------------------------------------------------------------------
extern "C" void kernel_launch(void* const* d_in, const int* in_sizes, int n_in,
                              void* d_out, int out_size) {
    const float* x  = (const float*)d_in[0];   // [N, 128]
    const int*   ei = (const int*)d_in[1];     // [2, E]
    const float* ea = (const float*)d_in[2];   // [E]
    const float* W  = (const float*)d_in[3];   // [256, 8]
    const float* b  = (const float*)d_in[4];   // [8]
    float* out = (float*)d_out;

    int N = in_sizes[0] / CC;
    int E = in_sizes[2];
    int M = E + N;
    const int* row = ei;
    const int* col = ei + E;

    float *p, *q, *s; unsigned int* m;
    cudaGetSymbolAddress((void**)&p, g_p);
    cudaGetSymbolAddress((void**)&q, g_q);
    cudaGetSymbolAddress((void**)&m, g_m);
    cudaGetSymbolAddress((void**)&s, g_s);

    int writeIdx = (out_size >= M * (HH + 2)) ? 1 : 0;

    int gblocks = (N + 7) / 8;   // one warp per node, 8 warps/block
    k_gemm<<<gblocks, 256>>>(x, W, p, q, m, s, N);

    int eblocks = (M + 255) / 256;
    k_passA<<<eblocks, 256>>>(row, col, ea, p, q, b, m, out, E, M, writeIdx);
    k_passB<<<eblocks, 256>>>(row, m, s, out, E, M);
    k_passC<<<eblocks, 256>>>(row, s, out, E, M);
}

// round 5
// speedup vs baseline: 1.9158x; 1.1955x over previous
#include <cuda_runtime.h>
#include <cuda_bf16.h>
#include <float.h>
#include <math.h>

#define HH 8
#define CC 128
#define MAXN 65536

// Scratch (allocation-free):
// p = x@W[:C], q = x@W[C:]  (L2-resident, N*8 floats each)
// m = per-node 8 x bf16 running max (16B), s = per-(node,head) f32 sum -> recip
__device__ float        g_p[MAXN * HH];
__device__ float        g_q[MAXN * HH];
__device__ unsigned int g_m[MAXN * 4];
__device__ float        g_s[MAXN * HH];

// ---------------------------------------------------------------------------
// vectorized reductions (sm_90+)
// ---------------------------------------------------------------------------
__device__ __forceinline__ void redMaxBf16v8(unsigned int* addr, const unsigned short* h) {
    asm volatile("red.global.max.noftz.v8.bf16 [%0], {%1,%2,%3,%4,%5,%6,%7,%8};"
                 :: "l"(addr), "h"(h[0]), "h"(h[1]), "h"(h[2]), "h"(h[3]),
                    "h"(h[4]), "h"(h[5]), "h"(h[6]), "h"(h[7]) : "memory");
}
__device__ __forceinline__ void redAddV4(float* addr, float a, float b, float c, float d) {
    asm volatile("red.global.add.v4.f32 [%0], {%1, %2, %3, %4};"
                 :: "l"(addr), "f"(a), "f"(b), "f"(c), "f"(d) : "memory");
}

// bf16 (packed in u32) -> float: widen exactly by moving to high 16 bits
__device__ __forceinline__ float bfLo(unsigned int u) { return __uint_as_float(u << 16); }
__device__ __forceinline__ float bfHi(unsigned int u) { return __uint_as_float(u & 0xFFFF0000u); }

// ---------------------------------------------------------------------------
// K1: p[n] = x[n] @ W[0:128], q[n] = x[n] @ W[128:256]   (one warp per node)
//     also initializes m[n] = bf16 -inf x8, s[n] = 0 x8
// ---------------------------------------------------------------------------
__global__ void k_gemm(const float* __restrict__ x, const float* __restrict__ W,
                       float* __restrict__ p, float* __restrict__ q,
                       unsigned int* __restrict__ m, float* __restrict__ s, int N) {
    __shared__ float ws[16][CC];
    for (int i = threadIdx.x; i < 256 * HH; i += blockDim.x) {
        int c = i / HH, h = i % HH;
        if (c < CC) ws[h][c] = W[i];
        else        ws[HH + h][c - CC] = W[i];
    }
    __syncthreads();

    int gwarp  = (blockIdx.x * blockDim.x + threadIdx.x) >> 5;
    int lane   = threadIdx.x & 31;
    int nwarps = (gridDim.x * blockDim.x) >> 5;

    for (int n = gwarp; n < N; n += nwarps) {
        float xv[4];
#pragma unroll
        for (int j = 0; j < 4; j++) xv[j] = x[n * CC + lane + 32 * j];

        float acc[16];
#pragma unroll
        for (int k = 0; k < 16; k++) acc[k] = 0.0f;
#pragma unroll
        for (int j = 0; j < 4; j++) {
            int c = lane + 32 * j;
#pragma unroll
            for (int k = 0; k < 16; k++) acc[k] += xv[j] * ws[k][c];
        }
#pragma unroll
        for (int off = 16; off; off >>= 1)
#pragma unroll
            for (int k = 0; k < 16; k++)
                acc[k] += __shfl_xor_sync(0xffffffffu, acc[k], off);

        if (lane < HH)          p[n * HH + lane]        = acc[lane];
        else if (lane < 2 * HH) q[n * HH + (lane - HH)] = acc[lane];
        else if (lane < 24)     s[n * HH + (lane - 16)] = 0.0f;
        else if (lane == 24)    *(uint4*)(m + n * 4) =
                                    make_uint4(0xFF80FF80u, 0xFF80FF80u,
                                               0xFF80FF80u, 0xFF80FF80u);
    }
}

// ---------------------------------------------------------------------------
// K2 (pass A): alpha = leaky((p[r]+q[c]+b)*|ea|)*100 -> out (staged, L2-hot)
//              one v8.bf16 red.max per edge; also write row/col outputs
// ---------------------------------------------------------------------------
__global__ void k_passA(const int* __restrict__ row, const int* __restrict__ col,
                        const float* __restrict__ ea,
                        const float* __restrict__ p, const float* __restrict__ q,
                        const float* __restrict__ b,
                        unsigned int* __restrict__ m, float* __restrict__ out,
                        int E, int M, int writeIdx) {
    int e = blockIdx.x * blockDim.x + threadIdx.x;
    if (e >= M) return;
    int r, c; float w;
    if (e < E) { r = row[e]; c = col[e]; w = fabsf(ea[e]); }
    else       { r = e - E;  c = r;      w = 1.0f; }

    float4 p0 = *(const float4*)(p + r * HH);
    float4 p1 = *(const float4*)(p + r * HH + 4);
    float4 q0 = *(const float4*)(q + c * HH);
    float4 q1 = *(const float4*)(q + c * HH + 4);

    float av[HH] = { p0.x + q0.x, p0.y + q0.y, p0.z + q0.z, p0.w + q0.w,
                     p1.x + q1.x, p1.y + q1.y, p1.z + q1.z, p1.w + q1.w };
    unsigned short hb[HH];
#pragma unroll
    for (int h = 0; h < HH; h++) {
        float t = (av[h] + b[h]) * w;
        t = (t > 0.0f) ? t : 0.2f * t;
        t *= 100.0f;
        av[h] = t;
        __nv_bfloat16 bh = __float2bfloat16_rn(t);
        hb[h] = *(unsigned short*)&bh;
    }
    redMaxBf16v8(&m[r * 4], hb);

    *(float4*)(out + (size_t)e * HH)     = make_float4(av[0], av[1], av[2], av[3]);
    *(float4*)(out + (size_t)e * HH + 4) = make_float4(av[4], av[5], av[6], av[7]);

    if (writeIdx) {
        out[(size_t)M * HH + e]     = (float)r;
        out[(size_t)M * HH + M + e] = (float)c;
    }
}

// ---------------------------------------------------------------------------
// K3 (pass B): read staged alpha (coalesced, L2), gather m (1 scattered load),
//              ev = exp(alpha - m); s[r] += ev; write ev back in place
// ---------------------------------------------------------------------------
__global__ void k_passB(const int* __restrict__ row,
                        const unsigned int* __restrict__ m, float* __restrict__ s,
                        float* __restrict__ out, int E, int M) {
    int e = blockIdx.x * blockDim.x + threadIdx.x;
    if (e >= M) return;
    int r = (e < E) ? row[e] : (e - E);

    float4 a0 = *(const float4*)(out + (size_t)e * HH);
    float4 a1 = *(const float4*)(out + (size_t)e * HH + 4);
    float av[HH] = { a0.x, a0.y, a0.z, a0.w, a1.x, a1.y, a1.z, a1.w };

    uint4 mu = *(const uint4*)(m + r * 4);
    float mv[HH] = { bfLo(mu.x), bfHi(mu.x), bfLo(mu.y), bfHi(mu.y),
                     bfLo(mu.z), bfHi(mu.z), bfLo(mu.w), bfHi(mu.w) };
    float ev[HH];
#pragma unroll
    for (int h = 0; h < HH; h++) ev[h] = __expf(av[h] - mv[h]);

    redAddV4(&s[r * HH],     ev[0], ev[1], ev[2], ev[3]);
    redAddV4(&s[r * HH + 4], ev[4], ev[5], ev[6], ev[7]);

    *(float4*)(out + (size_t)e * HH)     = make_float4(ev[0], ev[1], ev[2], ev[3]);
    *(float4*)(out + (size_t)e * HH + 4) = make_float4(ev[4], ev[5], ev[6], ev[7]);
}

// ---------------------------------------------------------------------------
// K3.5: sinv = 1 / (s + 1e-16)  per (node, head)  — hoists divides out of
//       the per-edge pass (each node's value reused by ~33 edges)
// ---------------------------------------------------------------------------
__global__ void k_rcp(float* __restrict__ s, int n8) {
    int i = blockIdx.x * blockDim.x + threadIdx.x;
    if (i < n8) s[i] = 1.0f / (s[i] + 1e-16f);
}

// ---------------------------------------------------------------------------
// K4 (pass C): read staged ev (coalesced), gather sinv (2 scattered), multiply
// ---------------------------------------------------------------------------
__global__ void k_passC(const int* __restrict__ row,
                        const float* __restrict__ s,
                        float* __restrict__ out, int E, int M) {
    int e = blockIdx.x * blockDim.x + threadIdx.x;
    if (e >= M) return;
    int r = (e < E) ? row[e] : (e - E);

    float4 e0 = *(const float4*)(out + (size_t)e * HH);
    float4 e1 = *(const float4*)(out + (size_t)e * HH + 4);
    float4 s0 = *(const float4*)(s + r * HH);
    float4 s1 = *(const float4*)(s + r * HH + 4);

    e0.x *= s0.x; e0.y *= s0.y; e0.z *= s0.z; e0.w *= s0.w;
    e1.x *= s1.x; e1.y *= s1.y; e1.z *= s1.z; e1.w *= s1.w;

    *(float4*)(out + (size_t)e * HH)     = e0;
    *(float4*)(out + (size_t)e * HH + 4) = e1;
}

// ---------------------------------------------------------------------------
extern "C" void kernel_launch(void* const* d_in, const int* in_sizes, int n_in,
                              void* d_out, int out_size) {
    const float* x  = (const float*)d_in[0];   // [N, 128]
    const int*   ei = (const int*)d_in[1];     // [2, E]
    const float* ea = (const float*)d_in[2];   // [E]
    const float* W  = (const float*)d_in[3];   // [256, 8]
    const float* b  = (const float*)d_in[4];   // [8]
    float* out = (float*)d_out;

    int N = in_sizes[0] / CC;
    int E = in_sizes[2];
    int M = E + N;
    const int* row = ei;
    const int* col = ei + E;

    float *p, *q, *s; unsigned int* m;
    cudaGetSymbolAddress((void**)&p, g_p);
    cudaGetSymbolAddress((void**)&q, g_q);
    cudaGetSymbolAddress((void**)&m, g_m);
    cudaGetSymbolAddress((void**)&s, g_s);

    int writeIdx = (out_size >= M * (HH + 2)) ? 1 : 0;

    int gblocks = (N + 7) / 8;   // one warp per node, 8 warps/block
    k_gemm<<<gblocks, 256>>>(x, W, p, q, m, s, N);

    int eblocks = (M + 255) / 256;
    k_passA<<<eblocks, 256>>>(row, col, ea, p, q, b, m, out, E, M, writeIdx);
    k_passB<<<eblocks, 256>>>(row, m, s, out, E, M);
    k_rcp<<<(N * HH + 255) / 256, 256>>>(s, N * HH);
    k_passC<<<eblocks, 256>>>(row, s, out, E, M);
}

// round 6
// speedup vs baseline: 2.4546x; 1.2812x over previous
#include <cuda_runtime.h>
#include <cuda_bf16.h>
#include <float.h>
#include <math.h>

#define HH 8
#define CC 128
#define MAXN 65536
#define GB_NODES 64
#define GB_THREADS 128

// Scratch (allocation-free):
// p = x@W[:C], q = x@W[C:]  (L2-resident, N*8 floats each)
// m = per-node 8 x bf16 running max (16B), s = per-(node,head) f32 sum -> recip
__device__ float        g_p[MAXN * HH];
__device__ float        g_q[MAXN * HH];
__device__ unsigned int g_m[MAXN * 4];
__device__ float        g_s[MAXN * HH];

// ---------------------------------------------------------------------------
// vectorized reductions (sm_90+)
// ---------------------------------------------------------------------------
__device__ __forceinline__ void redMaxBf16v8(unsigned int* addr, const unsigned short* h) {
    asm volatile("red.global.max.noftz.v8.bf16 [%0], {%1,%2,%3,%4,%5,%6,%7,%8};"
                 :: "l"(addr), "h"(h[0]), "h"(h[1]), "h"(h[2]), "h"(h[3]),
                    "h"(h[4]), "h"(h[5]), "h"(h[6]), "h"(h[7]) : "memory");
}
__device__ __forceinline__ void redAddV4(float* addr, float a, float b, float c, float d) {
    asm volatile("red.global.add.v4.f32 [%0], {%1, %2, %3, %4};"
                 :: "l"(addr), "f"(a), "f"(b), "f"(c), "f"(d) : "memory");
}

// bf16 (packed in u32) -> float: widen exactly by moving to high 16 bits
__device__ __forceinline__ float bfLo(unsigned int u) { return __uint_as_float(u << 16); }
__device__ __forceinline__ float bfHi(unsigned int u) { return __uint_as_float(u & 0xFFFF0000u); }

// ---------------------------------------------------------------------------
// K1: block-tile GEMM. 64 nodes/block, x tile transposed in shared.
// Thread (ng, kq) owns 4 nodes x 2 heads; integrates over all 128 columns.
// No cross-thread reduction. Also initializes m (bf16 -inf) and s (0).
// ---------------------------------------------------------------------------
__global__ __launch_bounds__(GB_THREADS)
void k_gemm(const float* __restrict__ x, const float* __restrict__ W,
            float* __restrict__ p, float* __restrict__ q,
            unsigned int* __restrict__ m, float* __restrict__ s, int N) {
    __shared__ float  ws[16][CC];       // ws[k][c]: k<8 -> Wp head k, k>=8 -> Wq
    __shared__ float4 xs4[CC][17];      // xs[c][node/4], stride 68 floats
    float* xsf = (float*)xs4;

    int tid   = threadIdx.x;
    int nbase = blockIdx.x * GB_NODES;

    // W: [256][8] row-major -> ws[k][c]
    for (int i = tid; i < 256 * HH; i += GB_THREADS) {
        int c = i >> 3, h = i & 7;
        if (c < CC) ws[h][c] = W[i];
        else        ws[HH + h][c - CC] = W[i];
    }

    // load x tile, store transposed (stride-68 pad -> 4-way STS conflict, OK)
    {
        int c4l = tid >> 2;      // 0..31 (float4 column index)
        int ro  = tid & 3;       // row offset
        for (int rb = 0; rb < GB_NODES; rb += 4) {
            int row = rb + ro;
            int n = nbase + row;
            if (n < N) {
                float4 v = *(const float4*)(x + (size_t)n * CC + c4l * 4);
                int cb = c4l * 4;
                xsf[(cb + 0) * 68 + row] = v.x;
                xsf[(cb + 1) * 68 + row] = v.y;
                xsf[(cb + 2) * 68 + row] = v.z;
                xsf[(cb + 3) * 68 + row] = v.w;
            }
        }
    }

    // init s = 0 and m = bf16 -inf for this block's nodes
    for (int i = tid; i < GB_NODES * HH; i += GB_THREADS) {
        int n = nbase + (i >> 3);
        if (n < N) s[n * HH + (i & 7)] = 0.0f;
    }
    if (tid < GB_NODES && nbase + tid < N)
        *(uint4*)(m + (nbase + tid) * 4) =
            make_uint4(0xFF80FF80u, 0xFF80FF80u, 0xFF80FF80u, 0xFF80FF80u);
    __syncthreads();

    int ng = tid & 15;          // node group (4 nodes)
    int kq = tid >> 4;          // 0..7 -> heads 2kq, 2kq+1
    int k0 = kq * 2;

    float a00 = 0, a01 = 0, a10 = 0, a11 = 0;
    float a20 = 0, a21 = 0, a30 = 0, a31 = 0;
#pragma unroll 4
    for (int c = 0; c < CC; c++) {
        float  w0 = ws[k0][c], w1 = ws[k0 + 1][c];
        float4 xv = xs4[c][ng];
        a00 += xv.x * w0; a01 += xv.x * w1;
        a10 += xv.y * w0; a11 += xv.y * w1;
        a20 += xv.z * w0; a21 += xv.z * w1;
        a30 += xv.w * w0; a31 += xv.w * w1;
    }
    float av0[4] = { a00, a10, a20, a30 };
    float av1[4] = { a01, a11, a21, a31 };
    float* dst = (k0 < HH) ? p : q;
    int h0 = (k0 < HH) ? k0 : k0 - HH;   // k0 even -> pair stays on one side
#pragma unroll
    for (int i = 0; i < 4; i++) {
        int n = nbase + ng * 4 + i;
        if (n < N) {
            dst[n * HH + h0]     = av0[i];
            dst[n * HH + h0 + 1] = av1[i];
        }
    }
}

// ---------------------------------------------------------------------------
// K2 (pass A): alpha = leaky((p[r]+q[c]+b)*|ea|)*100 -> out (staged, L2-hot)
//              one v8.bf16 red.max per edge; also write row/col outputs
// ---------------------------------------------------------------------------
__global__ void k_passA(const int* __restrict__ row, const int* __restrict__ col,
                        const float* __restrict__ ea,
                        const float* __restrict__ p, const float* __restrict__ q,
                        const float* __restrict__ b,
                        unsigned int* __restrict__ m, float* __restrict__ out,
                        int E, int M, int writeIdx) {
    int e = blockIdx.x * blockDim.x + threadIdx.x;
    if (e >= M) return;
    int r, c; float w;
    if (e < E) { r = row[e]; c = col[e]; w = fabsf(ea[e]); }
    else       { r = e - E;  c = r;      w = 1.0f; }

    float4 p0 = *(const float4*)(p + r * HH);
    float4 p1 = *(const float4*)(p + r * HH + 4);
    float4 q0 = *(const float4*)(q + c * HH);
    float4 q1 = *(const float4*)(q + c * HH + 4);

    float av[HH] = { p0.x + q0.x, p0.y + q0.y, p0.z + q0.z, p0.w + q0.w,
                     p1.x + q1.x, p1.y + q1.y, p1.z + q1.z, p1.w + q1.w };
    unsigned short hb[HH];
#pragma unroll
    for (int h = 0; h < HH; h++) {
        float t = (av[h] + b[h]) * w;
        t = (t > 0.0f) ? t : 0.2f * t;
        t *= 100.0f;
        av[h] = t;
        __nv_bfloat16 bh = __float2bfloat16_rn(t);
        hb[h] = *(unsigned short*)&bh;
    }
    redMaxBf16v8(&m[r * 4], hb);

    *(float4*)(out + (size_t)e * HH)     = make_float4(av[0], av[1], av[2], av[3]);
    *(float4*)(out + (size_t)e * HH + 4) = make_float4(av[4], av[5], av[6], av[7]);

    if (writeIdx) {
        __stcs(out + (size_t)M * HH + e,     (float)r);
        __stcs(out + (size_t)M * HH + M + e, (float)c);
    }
}

// ---------------------------------------------------------------------------
// K3 (pass B): read staged alpha (coalesced, L2), gather m (1 scattered load),
//              ev = exp(alpha - m); s[r] += ev; write ev back in place
// ---------------------------------------------------------------------------
__global__ void k_passB(const int* __restrict__ row,
                        const unsigned int* __restrict__ m, float* __restrict__ s,
                        float* __restrict__ out, int E, int M) {
    int e = blockIdx.x * blockDim.x + threadIdx.x;
    if (e >= M) return;
    int r = (e < E) ? row[e] : (e - E);

    float4 a0 = *(const float4*)(out + (size_t)e * HH);
    float4 a1 = *(const float4*)(out + (size_t)e * HH + 4);
    float av[HH] = { a0.x, a0.y, a0.z, a0.w, a1.x, a1.y, a1.z, a1.w };

    uint4 mu = *(const uint4*)(m + r * 4);
    float mv[HH] = { bfLo(mu.x), bfHi(mu.x), bfLo(mu.y), bfHi(mu.y),
                     bfLo(mu.z), bfHi(mu.z), bfLo(mu.w), bfHi(mu.w) };
    float ev[HH];
#pragma unroll
    for (int h = 0; h < HH; h++) ev[h] = __expf(av[h] - mv[h]);

    redAddV4(&s[r * HH],     ev[0], ev[1], ev[2], ev[3]);
    redAddV4(&s[r * HH + 4], ev[4], ev[5], ev[6], ev[7]);

    *(float4*)(out + (size_t)e * HH)     = make_float4(ev[0], ev[1], ev[2], ev[3]);
    *(float4*)(out + (size_t)e * HH + 4) = make_float4(ev[4], ev[5], ev[6], ev[7]);
}

// ---------------------------------------------------------------------------
// K3.5: sinv = 1 / (s + 1e-16)  per (node, head)
// ---------------------------------------------------------------------------
__global__ void k_rcp(float* __restrict__ s, int n8) {
    int i = blockIdx.x * blockDim.x + threadIdx.x;
    if (i < n8) s[i] = 1.0f / (s[i] + 1e-16f);
}

// ---------------------------------------------------------------------------
// K4 (pass C): read staged ev (coalesced), gather sinv (2 scattered), multiply
//              final stores use evict-first (never re-read)
// ---------------------------------------------------------------------------
__global__ void k_passC(const int* __restrict__ row,
                        const float* __restrict__ s,
                        float* __restrict__ out, int E, int M) {
    int e = blockIdx.x * blockDim.x + threadIdx.x;
    if (e >= M) return;
    int r = (e < E) ? row[e] : (e - E);

    float4 e0 = *(const float4*)(out + (size_t)e * HH);
    float4 e1 = *(const float4*)(out + (size_t)e * HH + 4);
    float4 s0 = *(const float4*)(s + r * HH);
    float4 s1 = *(const float4*)(s + r * HH + 4);

    e0.x *= s0.x; e0.y *= s0.y; e0.z *= s0.z; e0.w *= s0.w;
    e1.x *= s1.x; e1.y *= s1.y; e1.z *= s1.z; e1.w *= s1.w;

    __stcs((float4*)(out + (size_t)e * HH),     e0);
    __stcs((float4*)(out + (size_t)e * HH + 4), e1);
}

// ---------------------------------------------------------------------------
extern "C" void kernel_launch(void* const* d_in, const int* in_sizes, int n_in,
                              void* d_out, int out_size) {
    const float* x  = (const float*)d_in[0];   // [N, 128]
    const int*   ei = (const int*)d_in[1];     // [2, E]
    const float* ea = (const float*)d_in[2];   // [E]
    const float* W  = (const float*)d_in[3];   // [256, 8]
    const float* b  = (const float*)d_in[4];   // [8]
    float* out = (float*)d_out;

    int N = in_sizes[0] / CC;
    int E = in_sizes[2];
    int M = E + N;
    const int* row = ei;
    const int* col = ei + E;

    float *p, *q, *s; unsigned int* m;
    cudaGetSymbolAddress((void**)&p, g_p);
    cudaGetSymbolAddress((void**)&q, g_q);
    cudaGetSymbolAddress((void**)&m, g_m);
    cudaGetSymbolAddress((void**)&s, g_s);

    int writeIdx = (out_size >= M * (HH + 2)) ? 1 : 0;

    int gblocks = (N + GB_NODES - 1) / GB_NODES;
    k_gemm<<<gblocks, GB_THREADS>>>(x, W, p, q, m, s, N);

    int eblocks = (M + 255) / 256;
    k_passA<<<eblocks, 256>>>(row, col, ea, p, q, b, m, out, E, M, writeIdx);
    k_passB<<<eblocks, 256>>>(row, m, s, out, E, M);
    k_rcp<<<(N * HH + 255) / 256, 256>>>(s, N * HH);
    k_passC<<<eblocks, 256>>>(row, s, out, E, M);
}

// round 7
// speedup vs baseline: 2.5135x; 1.0240x over previous
#include <cuda_runtime.h>
#include <cuda_bf16.h>
#include <float.h>
#include <math.h>

#define HH 8
#define CC 128
#define MAXN 65536
#define GB_NODES 64
#define GB_THREADS 128

// Scratch (allocation-free), 32B-aligned so per-node 32B rows support v8 loads.
__device__ __align__(256) float        g_p[MAXN * HH];
__device__ __align__(256) float        g_q[MAXN * HH];
__device__ __align__(256) unsigned int g_m[MAXN * 4];
__device__ __align__(256) float        g_s[MAXN * HH];

// ---------------------------------------------------------------------------
// 256-bit scattered load (sm_100a / PTX ISA 8.7+): one LDG for a 32B node row
// ---------------------------------------------------------------------------
__device__ __forceinline__ void ldg256(const float* __restrict__ addr, float* v) {
    asm volatile("ld.global.v8.f32 {%0,%1,%2,%3,%4,%5,%6,%7}, [%8];"
                 : "=f"(v[0]), "=f"(v[1]), "=f"(v[2]), "=f"(v[3]),
                   "=f"(v[4]), "=f"(v[5]), "=f"(v[6]), "=f"(v[7])
                 : "l"(addr));
}

// ---------------------------------------------------------------------------
// vectorized reductions (sm_90+)
// ---------------------------------------------------------------------------
__device__ __forceinline__ void redMaxBf16v8(unsigned int* addr, const unsigned short* h) {
    asm volatile("red.global.max.noftz.v8.bf16 [%0], {%1,%2,%3,%4,%5,%6,%7,%8};"
                 :: "l"(addr), "h"(h[0]), "h"(h[1]), "h"(h[2]), "h"(h[3]),
                    "h"(h[4]), "h"(h[5]), "h"(h[6]), "h"(h[7]) : "memory");
}
__device__ __forceinline__ void redAddV4(float* addr, float a, float b, float c, float d) {
    asm volatile("red.global.add.v4.f32 [%0], {%1, %2, %3, %4};"
                 :: "l"(addr), "f"(a), "f"(b), "f"(c), "f"(d) : "memory");
}

// bf16 (packed in u32) -> float: widen exactly by moving to high 16 bits
__device__ __forceinline__ float bfLo(unsigned int u) { return __uint_as_float(u << 16); }
__device__ __forceinline__ float bfHi(unsigned int u) { return __uint_as_float(u & 0xFFFF0000u); }

// ---------------------------------------------------------------------------
// K1: block-tile GEMM. 64 nodes/block, x tile transposed in shared.
// Thread (ng, kq) owns 4 nodes x 2 heads; no cross-thread reduction.
// Also initializes m (bf16 -inf) and s (0).
// ---------------------------------------------------------------------------
__global__ __launch_bounds__(GB_THREADS)
void k_gemm(const float* __restrict__ x, const float* __restrict__ W,
            float* __restrict__ p, float* __restrict__ q,
            unsigned int* __restrict__ m, float* __restrict__ s, int N) {
    __shared__ float  ws[16][CC];       // ws[k][c]: k<8 -> Wp head k, k>=8 -> Wq
    __shared__ float4 xs4[CC][17];      // xs[c][node/4], stride 68 floats
    float* xsf = (float*)xs4;

    int tid   = threadIdx.x;
    int nbase = blockIdx.x * GB_NODES;

    for (int i = tid; i < 256 * HH; i += GB_THREADS) {
        int c = i >> 3, h = i & 7;
        if (c < CC) ws[h][c] = W[i];
        else        ws[HH + h][c - CC] = W[i];
    }

    {
        int c4l = tid >> 2;      // 0..31 (float4 column index)
        int ro  = tid & 3;       // row offset
        for (int rb = 0; rb < GB_NODES; rb += 4) {
            int row = rb + ro;
            int n = nbase + row;
            if (n < N) {
                float4 v = *(const float4*)(x + (size_t)n * CC + c4l * 4);
                int cb = c4l * 4;
                xsf[(cb + 0) * 68 + row] = v.x;
                xsf[(cb + 1) * 68 + row] = v.y;
                xsf[(cb + 2) * 68 + row] = v.z;
                xsf[(cb + 3) * 68 + row] = v.w;
            }
        }
    }

    for (int i = tid; i < GB_NODES * HH; i += GB_THREADS) {
        int n = nbase + (i >> 3);
        if (n < N) s[n * HH + (i & 7)] = 0.0f;
    }
    if (tid < GB_NODES && nbase + tid < N)
        *(uint4*)(m + (nbase + tid) * 4) =
            make_uint4(0xFF80FF80u, 0xFF80FF80u, 0xFF80FF80u, 0xFF80FF80u);
    __syncthreads();

    int ng = tid & 15;          // node group (4 nodes)
    int kq = tid >> 4;          // 0..7 -> heads 2kq, 2kq+1
    int k0 = kq * 2;

    float a00 = 0, a01 = 0, a10 = 0, a11 = 0;
    float a20 = 0, a21 = 0, a30 = 0, a31 = 0;
#pragma unroll 4
    for (int c = 0; c < CC; c++) {
        float  w0 = ws[k0][c], w1 = ws[k0 + 1][c];
        float4 xv = xs4[c][ng];
        a00 += xv.x * w0; a01 += xv.x * w1;
        a10 += xv.y * w0; a11 += xv.y * w1;
        a20 += xv.z * w0; a21 += xv.z * w1;
        a30 += xv.w * w0; a31 += xv.w * w1;
    }
    float av0[4] = { a00, a10, a20, a30 };
    float av1[4] = { a01, a11, a21, a31 };
    float* dst = (k0 < HH) ? p : q;
    int h0 = (k0 < HH) ? k0 : k0 - HH;
#pragma unroll
    for (int i = 0; i < 4; i++) {
        int n = nbase + ng * 4 + i;
        if (n < N) {
            dst[n * HH + h0]     = av0[i];
            dst[n * HH + h0 + 1] = av1[i];
        }
    }
}

// ---------------------------------------------------------------------------
// K2 (pass A): alpha = leaky((p[r]+q[c]+b)*|ea|)*100 -> out (staged, L2-hot)
//              p/q gathered with single 256-bit loads; one v8.bf16 red.max
// ---------------------------------------------------------------------------
__global__ void k_passA(const int* __restrict__ row, const int* __restrict__ col,
                        const float* __restrict__ ea,
                        const float* __restrict__ p, const float* __restrict__ q,
                        const float* __restrict__ b,
                        unsigned int* __restrict__ m, float* __restrict__ out,
                        int E, int M, int writeIdx) {
    int e = blockIdx.x * blockDim.x + threadIdx.x;
    if (e >= M) return;
    int r, c; float w;
    if (e < E) { r = row[e]; c = col[e]; w = fabsf(ea[e]); }
    else       { r = e - E;  c = r;      w = 1.0f; }

    float pv[HH], qv[HH];
    ldg256(p + r * HH, pv);
    ldg256(q + c * HH, qv);

    float av[HH];
    unsigned short hb[HH];
#pragma unroll
    for (int h = 0; h < HH; h++) {
        float t = (pv[h] + qv[h] + b[h]) * w;
        t = (t > 0.0f) ? t : 0.2f * t;
        t *= 100.0f;
        av[h] = t;
        __nv_bfloat16 bh = __float2bfloat16_rn(t);
        hb[h] = *(unsigned short*)&bh;
    }
    redMaxBf16v8(&m[r * 4], hb);

    *(float4*)(out + (size_t)e * HH)     = make_float4(av[0], av[1], av[2], av[3]);
    *(float4*)(out + (size_t)e * HH + 4) = make_float4(av[4], av[5], av[6], av[7]);

    if (writeIdx) {
        __stcs(out + (size_t)M * HH + e,     (float)r);
        __stcs(out + (size_t)M * HH + M + e, (float)c);
    }
}

// ---------------------------------------------------------------------------
// K3 (pass B): read staged alpha (coalesced), gather m (1 x 16B scattered),
//              ev = exp(alpha - m); s[r] += ev; write ev back in place
// ---------------------------------------------------------------------------
__global__ void k_passB(const int* __restrict__ row,
                        const unsigned int* __restrict__ m, float* __restrict__ s,
                        float* __restrict__ out, int E, int M) {
    int e = blockIdx.x * blockDim.x + threadIdx.x;
    if (e >= M) return;
    int r = (e < E) ? row[e] : (e - E);

    float4 a0 = *(const float4*)(out + (size_t)e * HH);
    float4 a1 = *(const float4*)(out + (size_t)e * HH + 4);
    float av[HH] = { a0.x, a0.y, a0.z, a0.w, a1.x, a1.y, a1.z, a1.w };

    uint4 mu = *(const uint4*)(m + r * 4);
    float mv[HH] = { bfLo(mu.x), bfHi(mu.x), bfLo(mu.y), bfHi(mu.y),
                     bfLo(mu.z), bfHi(mu.z), bfLo(mu.w), bfHi(mu.w) };
    float ev[HH];
#pragma unroll
    for (int h = 0; h < HH; h++) ev[h] = __expf(av[h] - mv[h]);

    redAddV4(&s[r * HH],     ev[0], ev[1], ev[2], ev[3]);
    redAddV4(&s[r * HH + 4], ev[4], ev[5], ev[6], ev[7]);

    *(float4*)(out + (size_t)e * HH)     = make_float4(ev[0], ev[1], ev[2], ev[3]);
    *(float4*)(out + (size_t)e * HH + 4) = make_float4(ev[4], ev[5], ev[6], ev[7]);
}

// ---------------------------------------------------------------------------
// K3.5: sinv = 1 / (s + 1e-16)  per (node, head)
// ---------------------------------------------------------------------------
__global__ void k_rcp(float* __restrict__ s, int n8) {
    int i = blockIdx.x * blockDim.x + threadIdx.x;
    if (i < n8) s[i] = 1.0f / (s[i] + 1e-16f);
}

// ---------------------------------------------------------------------------
// K4 (pass C): read staged ev (coalesced), gather sinv (1 x 256-bit), multiply
// ---------------------------------------------------------------------------
__global__ void k_passC(const int* __restrict__ row,
                        const float* __restrict__ s,
                        float* __restrict__ out, int E, int M) {
    int e = blockIdx.x * blockDim.x + threadIdx.x;
    if (e >= M) return;
    int r = (e < E) ? row[e] : (e - E);

    float4 e0 = *(const float4*)(out + (size_t)e * HH);
    float4 e1 = *(const float4*)(out + (size_t)e * HH + 4);
    float sv[HH];
    ldg256(s + r * HH, sv);

    e0.x *= sv[0]; e0.y *= sv[1]; e0.z *= sv[2]; e0.w *= sv[3];
    e1.x *= sv[4]; e1.y *= sv[5]; e1.z *= sv[6]; e1.w *= sv[7];

    __stcs((float4*)(out + (size_t)e * HH),     e0);
    __stcs((float4*)(out + (size_t)e * HH + 4), e1);
}

// ---------------------------------------------------------------------------
extern "C" void kernel_launch(void* const* d_in, const int* in_sizes, int n_in,
                              void* d_out, int out_size) {
    const float* x  = (const float*)d_in[0];   // [N, 128]
    const int*   ei = (const int*)d_in[1];     // [2, E]
    const float* ea = (const float*)d_in[2];   // [E]
    const float* W  = (const float*)d_in[3];   // [256, 8]
    const float* b  = (const float*)d_in[4];   // [8]
    float* out = (float*)d_out;

    int N = in_sizes[0] / CC;
    int E = in_sizes[2];
    int M = E + N;
    const int* row = ei;
    const int* col = ei + E;

    float *p, *q, *s; unsigned int* m;
    cudaGetSymbolAddress((void**)&p, g_p);
    cudaGetSymbolAddress((void**)&q, g_q);
    cudaGetSymbolAddress((void**)&m, g_m);
    cudaGetSymbolAddress((void**)&s, g_s);

    int writeIdx = (out_size >= M * (HH + 2)) ? 1 : 0;

    int gblocks = (N + GB_NODES - 1) / GB_NODES;
    k_gemm<<<gblocks, GB_THREADS>>>(x, W, p, q, m, s, N);

    int eblocks = (M + 255) / 256;
    k_passA<<<eblocks, 256>>>(row, col, ea, p, q, b, m, out, E, M, writeIdx);
    k_passB<<<eblocks, 256>>>(row, m, s, out, E, M);
    k_rcp<<<(N * HH + 255) / 256, 256>>>(s, N * HH);
    k_passC<<<eblocks, 256>>>(row, s, out, E, M);
}

// round 8
// speedup vs baseline: 2.7500x; 1.0941x over previous
#include <cuda_runtime.h>
#include <cuda_bf16.h>
#include <float.h>
#include <math.h>

#define HH 8
#define CC 128
#define MAXN 65536
#define GB_NODES 64
#define GB_THREADS 128
#define LOG2E 1.4426950408889634f

// Scratch (allocation-free), aligned so per-node 32B rows support v8 loads.
__device__ __align__(256) float        g_p[MAXN * HH];
__device__ __align__(256) float        g_q[MAXN * HH];
__device__ __align__(256) unsigned int g_m[MAXN * 4];
__device__ __align__(256) float        g_s[MAXN * HH];   // sum -> z = m + log2(s+eps)

// ---------------------------------------------------------------------------
// 256-bit scattered load (sm_100a): one LDG for a 32B node row
// ---------------------------------------------------------------------------
__device__ __forceinline__ void ldg256(const float* __restrict__ addr, float* v) {
    asm volatile("ld.global.v8.f32 {%0,%1,%2,%3,%4,%5,%6,%7}, [%8];"
                 : "=f"(v[0]), "=f"(v[1]), "=f"(v[2]), "=f"(v[3]),
                   "=f"(v[4]), "=f"(v[5]), "=f"(v[6]), "=f"(v[7])
                 : "l"(addr));
}

// ---------------------------------------------------------------------------
// vectorized reductions (sm_90+)
// ---------------------------------------------------------------------------
__device__ __forceinline__ void redMaxBf16v8(unsigned int* addr, const unsigned short* h) {
    asm volatile("red.global.max.noftz.v8.bf16 [%0], {%1,%2,%3,%4,%5,%6,%7,%8};"
                 :: "l"(addr), "h"(h[0]), "h"(h[1]), "h"(h[2]), "h"(h[3]),
                    "h"(h[4]), "h"(h[5]), "h"(h[6]), "h"(h[7]) : "memory");
}
__device__ __forceinline__ void redAddV4(float* addr, float a, float b, float c, float d) {
    asm volatile("red.global.add.v4.f32 [%0], {%1, %2, %3, %4};"
                 :: "l"(addr), "f"(a), "f"(b), "f"(c), "f"(d) : "memory");
}

// bf16 (packed in u32) -> float: widen exactly by moving to high 16 bits
__device__ __forceinline__ float bfLo(unsigned int u) { return __uint_as_float(u << 16); }
__device__ __forceinline__ float bfHi(unsigned int u) { return __uint_as_float(u & 0xFFFF0000u); }

// ---------------------------------------------------------------------------
// K1: block-tile GEMM. 64 nodes/block, x tile transposed in shared.
// Thread (ng, kq) owns 4 nodes x 2 heads; no cross-thread reduction.
// Also initializes m (bf16 -inf) and s (0).
// ---------------------------------------------------------------------------
__global__ __launch_bounds__(GB_THREADS)
void k_gemm(const float* __restrict__ x, const float* __restrict__ W,
            float* __restrict__ p, float* __restrict__ q,
            unsigned int* __restrict__ m, float* __restrict__ s, int N) {
    __shared__ float  ws[16][CC];       // ws[k][c]: k<8 -> Wp head k, k>=8 -> Wq
    __shared__ float4 xs4[CC][17];      // xs[c][node/4], stride 68 floats
    float* xsf = (float*)xs4;

    int tid   = threadIdx.x;
    int nbase = blockIdx.x * GB_NODES;

    for (int i = tid; i < 256 * HH; i += GB_THREADS) {
        int c = i >> 3, h = i & 7;
        if (c < CC) ws[h][c] = W[i];
        else        ws[HH + h][c - CC] = W[i];
    }

    {
        int c4l = tid >> 2;      // 0..31 (float4 column index)
        int ro  = tid & 3;       // row offset
        for (int rb = 0; rb < GB_NODES; rb += 4) {
            int row = rb + ro;
            int n = nbase + row;
            if (n < N) {
                float4 v = *(const float4*)(x + (size_t)n * CC + c4l * 4);
                int cb = c4l * 4;
                xsf[(cb + 0) * 68 + row] = v.x;
                xsf[(cb + 1) * 68 + row] = v.y;
                xsf[(cb + 2) * 68 + row] = v.z;
                xsf[(cb + 3) * 68 + row] = v.w;
            }
        }
    }

    for (int i = tid; i < GB_NODES * HH; i += GB_THREADS) {
        int n = nbase + (i >> 3);
        if (n < N) s[n * HH + (i & 7)] = 0.0f;
    }
    if (tid < GB_NODES && nbase + tid < N)
        *(uint4*)(m + (nbase + tid) * 4) =
            make_uint4(0xFF80FF80u, 0xFF80FF80u, 0xFF80FF80u, 0xFF80FF80u);
    __syncthreads();

    int ng = tid & 15;          // node group (4 nodes)
    int kq = tid >> 4;          // 0..7 -> heads 2kq, 2kq+1
    int k0 = kq * 2;

    float a00 = 0, a01 = 0, a10 = 0, a11 = 0;
    float a20 = 0, a21 = 0, a30 = 0, a31 = 0;
#pragma unroll 4
    for (int c = 0; c < CC; c++) {
        float  w0 = ws[k0][c], w1 = ws[k0 + 1][c];
        float4 xv = xs4[c][ng];
        a00 += xv.x * w0; a01 += xv.x * w1;
        a10 += xv.y * w0; a11 += xv.y * w1;
        a20 += xv.z * w0; a21 += xv.z * w1;
        a30 += xv.w * w0; a31 += xv.w * w1;
    }
    float av0[4] = { a00, a10, a20, a30 };
    float av1[4] = { a01, a11, a21, a31 };
    float* dst = (k0 < HH) ? p : q;
    int h0 = (k0 < HH) ? k0 : k0 - HH;
#pragma unroll
    for (int i = 0; i < 4; i++) {
        int n = nbase + ng * 4 + i;
        if (n < N) {
            dst[n * HH + h0]     = av0[i];
            dst[n * HH + h0 + 1] = av1[i];
        }
    }
}

// ---------------------------------------------------------------------------
// K2 (pass A): a2 = leaky((p[r]+q[c]+b)*|ea|)*100*log2e -> out (staged)
//              one v8.bf16 red.max per edge; also write row/col outputs
// ---------------------------------------------------------------------------
__global__ void k_passA(const int* __restrict__ row, const int* __restrict__ col,
                        const float* __restrict__ ea,
                        const float* __restrict__ p, const float* __restrict__ q,
                        const float* __restrict__ b,
                        unsigned int* __restrict__ m, float* __restrict__ out,
                        int E, int M, int writeIdx) {
    int e = blockIdx.x * blockDim.x + threadIdx.x;
    if (e >= M) return;
    int r, c; float w;
    if (e < E) { r = row[e]; c = col[e]; w = fabsf(ea[e]); }
    else       { r = e - E;  c = r;      w = 1.0f; }

    float pv[HH], qv[HH];
    ldg256(p + r * HH, pv);
    ldg256(q + c * HH, qv);

    float av[HH];
    unsigned short hb[HH];
#pragma unroll
    for (int h = 0; h < HH; h++) {
        float t = (pv[h] + qv[h] + b[h]) * w;
        t = (t > 0.0f) ? t : 0.2f * t;
        t *= 100.0f * LOG2E;            // stage in log2 domain, exp2-ready
        av[h] = t;
        __nv_bfloat16 bh = __float2bfloat16_rn(t);
        hb[h] = *(unsigned short*)&bh;
    }
    redMaxBf16v8(&m[r * 4], hb);

    *(float4*)(out + (size_t)e * HH)     = make_float4(av[0], av[1], av[2], av[3]);
    *(float4*)(out + (size_t)e * HH + 4) = make_float4(av[4], av[5], av[6], av[7]);

    if (writeIdx) {
        __stcs(out + (size_t)M * HH + e,     (float)r);
        __stcs(out + (size_t)M * HH + M + e, (float)c);
    }
}

// ---------------------------------------------------------------------------
// K3 (pass B): read staged a2 (coalesced), gather m (1 x 16B scattered),
//              s[r] += exp2(a2 - m). NO writeback.
// ---------------------------------------------------------------------------
__global__ void k_passB(const int* __restrict__ row,
                        const unsigned int* __restrict__ m, float* __restrict__ s,
                        const float* __restrict__ out, int E, int M) {
    int e = blockIdx.x * blockDim.x + threadIdx.x;
    if (e >= M) return;
    int r = (e < E) ? row[e] : (e - E);

    float4 a0 = *(const float4*)(out + (size_t)e * HH);
    float4 a1 = *(const float4*)(out + (size_t)e * HH + 4);
    float av[HH] = { a0.x, a0.y, a0.z, a0.w, a1.x, a1.y, a1.z, a1.w };

    uint4 mu = *(const uint4*)(m + r * 4);
    float mv[HH] = { bfLo(mu.x), bfHi(mu.x), bfLo(mu.y), bfHi(mu.y),
                     bfLo(mu.z), bfHi(mu.z), bfLo(mu.w), bfHi(mu.w) };
    float ev[HH];
#pragma unroll
    for (int h = 0; h < HH; h++) ev[h] = exp2f(av[h] - mv[h]);

    redAddV4(&s[r * HH],     ev[0], ev[1], ev[2], ev[3]);
    redAddV4(&s[r * HH + 4], ev[4], ev[5], ev[6], ev[7]);
}

// ---------------------------------------------------------------------------
// K3.5: z = m + log2(s + 1e-16) per (node, head), f32, in place over s
// ---------------------------------------------------------------------------
__global__ void k_z(const unsigned int* __restrict__ m, float* __restrict__ s, int N) {
    int n = blockIdx.x * blockDim.x + threadIdx.x;
    if (n >= N) return;
    uint4 mu = *(const uint4*)(m + n * 4);
    float mv[HH] = { bfLo(mu.x), bfHi(mu.x), bfLo(mu.y), bfHi(mu.y),
                     bfLo(mu.z), bfHi(mu.z), bfLo(mu.w), bfHi(mu.w) };
    float4 s0 = *(const float4*)(s + n * HH);
    float4 s1 = *(const float4*)(s + n * HH + 4);
    float sv[HH] = { s0.x, s0.y, s0.z, s0.w, s1.x, s1.y, s1.z, s1.w };
    float zv[HH];
#pragma unroll
    for (int h = 0; h < HH; h++) zv[h] = mv[h] + __log2f(sv[h] + 1e-16f);
    *(float4*)(s + n * HH)     = make_float4(zv[0], zv[1], zv[2], zv[3]);
    *(float4*)(s + n * HH + 4) = make_float4(zv[4], zv[5], zv[6], zv[7]);
}

// ---------------------------------------------------------------------------
// K4 (pass C): read staged a2 (last-use), gather z (1 x 256-bit),
//              out = exp2(a2 - z), evict-first final store
// ---------------------------------------------------------------------------
__global__ void k_passC(const int* __restrict__ row,
                        const float* __restrict__ s,
                        float* __restrict__ out, int E, int M) {
    int e = blockIdx.x * blockDim.x + threadIdx.x;
    if (e >= M) return;
    int r = (e < E) ? row[e] : (e - E);

    float4 a0 = __ldlu((const float4*)(out + (size_t)e * HH));
    float4 a1 = __ldlu((const float4*)(out + (size_t)e * HH + 4));
    float av[HH] = { a0.x, a0.y, a0.z, a0.w, a1.x, a1.y, a1.z, a1.w };

    float zv[HH];
    ldg256(s + r * HH, zv);

#pragma unroll
    for (int h = 0; h < HH; h++) av[h] = exp2f(av[h] - zv[h]);

    __stcs((float4*)(out + (size_t)e * HH),
           make_float4(av[0], av[1], av[2], av[3]));
    __stcs((float4*)(out + (size_t)e * HH + 4),
           make_float4(av[4], av[5], av[6], av[7]));
}

// ---------------------------------------------------------------------------
extern "C" void kernel_launch(void* const* d_in, const int* in_sizes, int n_in,
                              void* d_out, int out_size) {
    const float* x  = (const float*)d_in[0];   // [N, 128]
    const int*   ei = (const int*)d_in[1];     // [2, E]
    const float* ea = (const float*)d_in[2];   // [E]
    const float* W  = (const float*)d_in[3];   // [256, 8]
    const float* b  = (const float*)d_in[4];   // [8]
    float* out = (float*)d_out;

    int N = in_sizes[0] / CC;
    int E = in_sizes[2];
    int M = E + N;
    const int* row = ei;
    const int* col = ei + E;

    float *p, *q, *s; unsigned int* m;
    cudaGetSymbolAddress((void**)&p, g_p);
    cudaGetSymbolAddress((void**)&q, g_q);
    cudaGetSymbolAddress((void**)&m, g_m);
    cudaGetSymbolAddress((void**)&s, g_s);

    int writeIdx = (out_size >= M * (HH + 2)) ? 1 : 0;

    int gblocks = (N + GB_NODES - 1) / GB_NODES;
    k_gemm<<<gblocks, GB_THREADS>>>(x, W, p, q, m, s, N);

    int eblocks = (M + 255) / 256;
    k_passA<<<eblocks, 256>>>(row, col, ea, p, q, b, m, out, E, M, writeIdx);
    k_passB<<<eblocks, 256>>>(row, m, s, out, E, M);
    k_z<<<(N + 255) / 256, 256>>>(m, s, N);
    k_passC<<<eblocks, 256>>>(row, s, out, E, M);
}